// round 10
// baseline (speedup 1.0000x reference)
#include <cuda_runtime.h>
#include <cuda_bf16.h>
#include <math.h>

// mma.sync bf16 hi/lo-split conv + min + softmax, with B-fragment register caching.
// CTA = (n, h, px-half). Per depth d: D[co32, px64] = sum_kd W[kd] . X(z=d+kd).
// X-slice B-frags live in registers for their full 3-depth lifetime (rotation via
// manual 3x depth unroll); only the newly built slice is ldsm'd each depth.

typedef unsigned int u32;

#define XROW 144                        // 66 px cols * 2B, padded to 16B mult
#define XPART (32 * XROW)               // 4608
#define XSLOT (2 * XPART)               // 9216 (hi+lo)
#define OFF_X 0
#define OFF_W (4 * XSLOT)               // 36864
#define WROW 192
#define WPART (32 * WROW)               // 6144
#define SMEM_TOTAL (OFF_W + 2 * WPART + 64)   // 49216

__device__ __forceinline__ void ldsm4(u32* r, u32 a) {
    asm volatile("ldmatrix.sync.aligned.m8n8.x4.shared.b16 {%0,%1,%2,%3}, [%4];"
        : "=r"(r[0]), "=r"(r[1]), "=r"(r[2]), "=r"(r[3]) : "r"(a));
}
__device__ __forceinline__ void ldsm4t(u32* r, u32 a) {
    asm volatile("ldmatrix.sync.aligned.m8n8.x4.trans.shared.b16 {%0,%1,%2,%3}, [%4];"
        : "=r"(r[0]), "=r"(r[1]), "=r"(r[2]), "=r"(r[3]) : "r"(a));
}
__device__ __forceinline__ void mma_bf16(float* d, const u32* a, u32 b0, u32 b1) {
    asm volatile(
        "mma.sync.aligned.m16n8k16.row.col.f32.bf16.bf16.f32 "
        "{%0,%1,%2,%3}, {%4,%5,%6,%7}, {%8,%9}, {%0,%1,%2,%3};"
        : "+f"(d[0]), "+f"(d[1]), "+f"(d[2]), "+f"(d[3])
        : "r"(a[0]), "r"(a[1]), "r"(a[2]), "r"(a[3]), "r"(b0), "r"(b1));
}

extern "C" __global__ void __launch_bounds__(256, 2)
conv_mma(const float* __restrict__ x, const float* __restrict__ wgt,
         const float* __restrict__ bias, float* __restrict__ out)
{
    extern __shared__ char sm[];
    const u32 sb = (u32)__cvta_generic_to_shared(sm);
    const int tid   = threadIdx.x;
    const int lane  = tid & 31;
    const int wid   = tid >> 5;
    const int mtile = wid & 1;          // co 16-row tile
    const int npair = wid >> 1;         // px base npair*16 (2 n8-tiles)
    const int h = blockIdx.x;
    const int n = blockIdx.y;
    const int P = blockIdx.z << 6;      // px-half base: 0 or 64

    // zero smem (k-pad rows 27-31, co-pad, px-pad stay 0)
    for (int i = tid; i < SMEM_TOTAL / 16; i += 256)
        *reinterpret_cast<float4*>(sm + i * 16) = make_float4(0.f, 0.f, 0.f, 0.f);
    __syncthreads();

    // ---- weights -> smem bf16 hi/lo: W[part][co][k], k = kd*32 + r9*3 + kw ----
    for (int e = tid; e < 1944; e += 256) {
        int co = e / 81, tap = e % 81;
        int kd = (tap % 27) / 9;
        int r9 = (tap / 27) * 3 + (tap % 9) / 3;   // ci*3 + kh
        int kw = tap % 3;
        float v = wgt[e];
        __nv_bfloat16 hb = __float2bfloat16(v);
        __nv_bfloat16 lb = __float2bfloat16(v - __bfloat162float(hb));
        int k = kd * 32 + r9 * 3 + kw;
        *reinterpret_cast<__nv_bfloat16*>(sm + OFF_W +         co * WROW + k * 2) = hb;
        *reinterpret_cast<__nv_bfloat16*>(sm + OFF_W + WPART + co * WROW + k * 2) = lb;
    }

    // ---- slice builder: z -> slot; rows k=r9*3+kw, 66 local px cols ----
    auto build = [&](int z, int slot) {
        if (z >= 32) return;
        char* base = sm + OFF_X + slot * XSLOT;
        #pragma unroll
        for (int it = 0; it < 3; ++it) {
            int idx = tid + it * 256;
            if (idx < 594) {
                int r9  = idx / 66;
                int pxl = idx - r9 * 66;
                int ci  = r9 / 3, kh = r9 % 3;
                float v = 0.f;
                if (P + pxl < 128)
                    v = __ldg(x + ((size_t)((n * 3 + ci) * 32 + z) << 14)
                                + ((h + kh) << 7) + P + pxl);
                __nv_bfloat16 hb = __float2bfloat16(v);
                __nv_bfloat16 lb = __float2bfloat16(v - __bfloat162float(hb));
                #pragma unroll
                for (int kw = 0; kw < 3; ++kw) {
                    int col = pxl - kw;
                    if (col >= 0) {
                        int k = r9 * 3 + kw;
                        *reinterpret_cast<__nv_bfloat16*>(base + k * XROW + col * 2) = hb;
                        *reinterpret_cast<__nv_bfloat16*>(base + XPART + k * XROW + col * 2) = lb;
                    }
                }
            }
        }
    };

    build(0, 0); build(1, 1); build(2, 2);
    __syncthreads();

    // ---- persistent A fragments (weights) ----
    u32 ah[3][2][4], al[3][2][4];
    {
        u32 rowb = sb + OFF_W + (u32)((mtile * 16 + (lane & 15)) * WROW + (lane >> 4) * 16);
        #pragma unroll
        for (int kd = 0; kd < 3; ++kd)
            #pragma unroll
            for (int ks = 0; ks < 2; ++ks) {
                ldsm4(ah[kd][ks], rowb + (u32)((kd * 32 + ks * 16) * 2));
                ldsm4(al[kd][ks], rowb + (u32)(WPART + (kd * 32 + ks * 16) * 2));
            }
    }

    // B-frag lane base (ldsm.x4.trans over k16 x px16)
    const int krow = ((lane >> 3) & 1) * 8 + (lane & 7);
    const int pxo  = (lane >> 4) * 8;
    const u32 boff = sb + OFF_X + (u32)(krow * XROW + (npair * 16 + pxo) * 2);

    // load all 4 x4-frags (ks2 x hi/lo) for a slice slot into f[16]
    auto load_frags = [&](u32* f, int slot) {
        const u32 a0 = boff + (u32)(slot * XSLOT);
        #pragma unroll
        for (int ks = 0; ks < 2; ++ks) {
            ldsm4t(f + ks * 8,     a0 + (u32)(ks * 16 * XROW));          // hi
            ldsm4t(f + ks * 8 + 4, a0 + (u32)(XPART + ks * 16 * XROW)); // lo
        }
    };

    const float INF = __int_as_float(0x7f800000);
    float mn[2][4];
    #pragma unroll
    for (int t = 0; t < 2; ++t)
        #pragma unroll
        for (int e = 0; e < 4; ++e) mn[t][e] = INF;

    // depth body: F0/F1/F2 = frags of slices d, d+1, d+2 (kd = 0,1,2)
    auto depth_body = [&](const u32* F0, const u32* F1, const u32* F2) {
        float D[2][4];
        #pragma unroll
        for (int t = 0; t < 2; ++t)
            #pragma unroll
            for (int e = 0; e < 4; ++e) D[t][e] = 0.f;
        const u32* F[3] = {F0, F1, F2};
        #pragma unroll
        for (int kd = 0; kd < 3; ++kd) {
            #pragma unroll
            for (int ks = 0; ks < 2; ++ks) {
                const u32* bh = F[kd] + ks * 8;
                const u32* bl = bh + 4;
                #pragma unroll
                for (int nt = 0; nt < 2; ++nt) {
                    mma_bf16(D[nt], ah[kd][ks], bh[nt * 2], bh[nt * 2 + 1]);
                    mma_bf16(D[nt], al[kd][ks], bh[nt * 2], bh[nt * 2 + 1]);
                    mma_bf16(D[nt], ah[kd][ks], bl[nt * 2], bl[nt * 2 + 1]);
                }
            }
        }
        #pragma unroll
        for (int t = 0; t < 2; ++t)
            #pragma unroll
            for (int e = 0; e < 4; ++e) mn[t][e] = fminf(mn[t][e], D[t][e]);
    };

    u32 FA[16], FB[16], FC[16];
    load_frags(FA, 0);                  // slice 0
    load_frags(FB, 1);                  // slice 1

    #pragma unroll 1
    for (int db = 0; db < 30; db += 3) {
        load_frags(FC, (db + 2) & 3);   // slice db+2 (built, synced)
        depth_body(FA, FB, FC);
        build(db + 3, (db + 3) & 3);
        __syncthreads();

        load_frags(FA, (db + 3) & 3);   // slice db+3
        depth_body(FB, FC, FA);
        build(db + 4, (db + 4) & 3);
        __syncthreads();

        load_frags(FB, (db + 4) & 3);   // slice db+4
        depth_body(FC, FA, FB);
        build(db + 5, (db + 5) & 3);
        __syncthreads();
    }

    // ---- scatter min to sf[px64][co32], bias+softmax ----
    float* sf = reinterpret_cast<float*>(sm);   // aliases X region (reads done)
    {
        const int cob = mtile * 16 + (lane >> 2);
        const int pxb = npair * 16 + (lane & 3) * 2;
        #pragma unroll
        for (int nt = 0; nt < 2; ++nt) {
            int px = pxb + nt * 8;
            sf[px * 32 + cob]           = mn[nt][0];
            sf[(px + 1) * 32 + cob]     = mn[nt][1];
            sf[px * 32 + cob + 8]       = mn[nt][2];
            sf[(px + 1) * 32 + cob + 8] = mn[nt][3];
        }
    }
    __syncthreads();

    if (tid < 64 && P + tid < 126) {
        float v[24];
        float m = -INF;
        #pragma unroll
        for (int c = 0; c < 24; ++c) {
            v[c] = sf[tid * 32 + c] + __ldg(&bias[c]);
            m = fmaxf(m, v[c]);
        }
        float s = 0.f;
        #pragma unroll
        for (int c = 0; c < 24; ++c) { v[c] = __expf(v[c] - m); s += v[c]; }
        const float inv = 1.0f / s;
        float* op = out + (size_t)n * 24 * 15876 + (size_t)h * 126 + P + tid;
        #pragma unroll
        for (int c = 0; c < 24; ++c)
            op[(size_t)c * 15876] = v[c] * inv;
    }
}

extern "C" void kernel_launch(void* const* d_in, const int* in_sizes, int n_in,
                              void* d_out, int out_size) {
    const float* x    = (const float*)d_in[0];
    const float* wgt  = (const float*)d_in[1];
    const float* bias = (const float*)d_in[2];
    float* out        = (float*)d_out;

    cudaFuncSetAttribute(conv_mma,
                         cudaFuncAttributeMaxDynamicSharedMemorySize, SMEM_TOTAL);

    dim3 grid(126, 16, 2);   // (h, n, px-half)
    conv_mma<<<grid, 256, SMEM_TOTAL>>>(x, wgt, bias, out);
}

// round 11
// speedup vs baseline: 1.2094x; 1.2094x over previous
#include <cuda_runtime.h>
#include <cuda_bf16.h>
#include <math.h>

// mma.sync bf16 hi/lo split, operand-swapped: A = x (M=px 128), B = weights (N=co 24).
// CTA = (n, h). Per depth d: D[px128, co24] = sum_kd X(z=d+kd)[px,k] . W[kd][k,co].
// Weights persistent as B-fragments (72 regs); per depth only the x A-frags are
// ldsm'd (12 x4/warp). Ring-4 slices, build LDG prefetched into regs. Min + softmax.

typedef unsigned int u32;

#define XROW 80                          // bytes per px row (32 k * 2B + 16 pad)
#define XPART (128 * XROW)               // 10240
#define XSLOT (2 * XPART)                // 20480 (hi+lo)
#define OFF_X 0
#define OFF_W (4 * XSLOT)                // 81920
#define WROW 64                          // 32 co * 2B
#define WPART (96 * WROW)                // 6144: [kd3][k32][co32]
#define SMEM_TOTAL (OFF_W + 2 * WPART + 64)   // 94272

__device__ __forceinline__ void ldsm4(u32* r, u32 a) {
    asm volatile("ldmatrix.sync.aligned.m8n8.x4.shared.b16 {%0,%1,%2,%3}, [%4];"
        : "=r"(r[0]), "=r"(r[1]), "=r"(r[2]), "=r"(r[3]) : "r"(a));
}
__device__ __forceinline__ void ldsm4t(u32* r, u32 a) {
    asm volatile("ldmatrix.sync.aligned.m8n8.x4.trans.shared.b16 {%0,%1,%2,%3}, [%4];"
        : "=r"(r[0]), "=r"(r[1]), "=r"(r[2]), "=r"(r[3]) : "r"(a));
}
__device__ __forceinline__ void ldsm2t(u32* r, u32 a) {
    asm volatile("ldmatrix.sync.aligned.m8n8.x2.trans.shared.b16 {%0,%1}, [%2];"
        : "=r"(r[0]), "=r"(r[1]) : "r"(a));
}
__device__ __forceinline__ void mma_bf16(float* d, const u32* a, u32 b0, u32 b1) {
    asm volatile(
        "mma.sync.aligned.m16n8k16.row.col.f32.bf16.bf16.f32 "
        "{%0,%1,%2,%3}, {%4,%5,%6,%7}, {%8,%9}, {%0,%1,%2,%3};"
        : "+f"(d[0]), "+f"(d[1]), "+f"(d[2]), "+f"(d[3])
        : "r"(a[0]), "r"(a[1]), "r"(a[2]), "r"(a[3]), "r"(b0), "r"(b1));
}

extern "C" __global__ void __launch_bounds__(256, 2)
conv_mma(const float* __restrict__ x, const float* __restrict__ wgt,
         const float* __restrict__ bias, float* __restrict__ out)
{
    extern __shared__ char sm[];
    const u32 sb = (u32)__cvta_generic_to_shared(sm);
    const int tid  = threadIdx.x;
    const int lane = tid & 31;
    const int wid  = tid >> 5;            // px M-tile: rows wid*16..+15
    const int h = blockIdx.x;
    const int n = blockIdx.y;

    // zero smem (k 27-31, co 24-31 pads stay 0 forever)
    for (int i = tid; i < SMEM_TOTAL / 16; i += 256)
        *reinterpret_cast<float4*>(sm + i * 16) = make_float4(0.f, 0.f, 0.f, 0.f);
    __syncthreads();

    // ---- weights -> smem bf16 hi/lo: W[part][kd][k][co], k=(ci*3+kh)*3+kw ----
    for (int e = tid; e < 1944; e += 256) {
        int co = e / 81, tap = e % 81;
        int ci = tap / 27;
        int kd = (tap % 27) / 9;
        int kh = (tap % 9) / 3;
        int kw = tap % 3;
        float v = wgt[e];
        __nv_bfloat16 hb = __float2bfloat16(v);
        __nv_bfloat16 lb = __float2bfloat16(v - __bfloat162float(hb));
        int k = (ci * 3 + kh) * 3 + kw;
        int row = kd * 32 + k;
        *reinterpret_cast<__nv_bfloat16*>(sm + OFF_W +         row * WROW + co * 2) = hb;
        *reinterpret_cast<__nv_bfloat16*>(sm + OFF_W + WPART + row * WROW + co * 2) = lb;
    }

    // ---- build: LDG phase (regs) + STS phase, source-driven ----
    // source idx = r9*128 + pxs, r9 = ci*3+kh; each source -> 3 (k,px) slots, hi+lo
    float pv[5];
    auto build_ld = [&](int z) {
        if (z >= 32) return;
        #pragma unroll
        for (int it = 0; it < 5; ++it) {
            int idx = tid + it * 256;
            if (idx < 1152) {
                int r9  = idx >> 7;
                int pxs = idx & 127;
                int ci  = r9 / 3, kh = r9 % 3;
                pv[it] = __ldg(x + ((size_t)((n * 3 + ci) * 32 + z) << 14)
                                 + ((h + kh) << 7) + pxs);
            }
        }
    };
    auto build_st = [&](int z, int slot) {
        if (z >= 32) return;
        char* base = sm + OFF_X + slot * XSLOT;
        #pragma unroll
        for (int it = 0; it < 5; ++it) {
            int idx = tid + it * 256;
            if (idx < 1152) {
                int r9  = idx >> 7;
                int pxs = idx & 127;
                __nv_bfloat16 hb = __float2bfloat16(pv[it]);
                __nv_bfloat16 lb = __float2bfloat16(pv[it] - __bfloat162float(hb));
                #pragma unroll
                for (int kw = 0; kw < 3; ++kw) {
                    int px = pxs - kw;
                    if (px >= 0) {
                        int k = r9 * 3 + kw;
                        *reinterpret_cast<__nv_bfloat16*>(base + px * XROW + k * 2) = hb;
                        *reinterpret_cast<__nv_bfloat16*>(base + XPART + px * XROW + k * 2) = lb;
                    }
                }
            }
        }
    };

    build_ld(0); build_st(0, 0);
    build_ld(1); build_st(1, 1);
    build_ld(2); build_st(2, 2);
    __syncthreads();

    // ---- persistent weight B-fragments: Bh/Bl[kd][ks][6] (nt0,nt1 from x4, nt2 x2) ----
    u32 Bh[3][2][6], Bl[3][2][6];
    {
        const u32 wb = sb + OFF_W;
        const int krow = lane & 15;
        const int coo  = (lane >> 4) * 8;
        #pragma unroll
        for (int kd = 0; kd < 3; ++kd)
            #pragma unroll
            for (int ks = 0; ks < 2; ++ks) {
                u32 rbase = (u32)((kd * 32 + ks * 16 + krow) * WROW);
                ldsm4t(Bh[kd][ks],     wb + rbase + (u32)(coo * 2));
                ldsm2t(Bh[kd][ks] + 4, wb + rbase + 32);            // co 16-23
                ldsm4t(Bl[kd][ks],     wb + WPART + rbase + (u32)(coo * 2));
                ldsm2t(Bl[kd][ks] + 4, wb + WPART + rbase + 32);
            }
    }

    // A-frag (x) lane base: row = wid*16 + (lane&15), 16B col block = lane>>4
    const u32 abase = sb + OFF_X + (u32)((wid * 16 + (lane & 15)) * XROW + (lane >> 4) * 16);

    const float INF = __int_as_float(0x7f800000);
    float mn[3][4];
    #pragma unroll
    for (int t = 0; t < 3; ++t)
        #pragma unroll
        for (int e = 0; e < 4; ++e) mn[t][e] = INF;

    #pragma unroll 1
    for (int d = 0; d < 30; ++d) {
        build_ld(d + 3);                        // LDG into regs (hides DRAM)

        float D[3][4];
        #pragma unroll
        for (int t = 0; t < 3; ++t)
            #pragma unroll
            for (int e = 0; e < 4; ++e) D[t][e] = 0.f;

        #pragma unroll
        for (int kd = 0; kd < 3; ++kd) {
            const u32 sa = abase + (u32)(((d + kd) & 3) * XSLOT);
            #pragma unroll
            for (int ks = 0; ks < 2; ++ks) {
                u32 Ah[4], Al[4];
                ldsm4(Ah, sa + (u32)(ks * 32));
                ldsm4(Al, sa + (u32)(XPART + ks * 32));
                #pragma unroll
                for (int nt = 0; nt < 3; ++nt) {
                    mma_bf16(D[nt], Ah, Bh[kd][ks][2 * nt], Bh[kd][ks][2 * nt + 1]); // hh
                    mma_bf16(D[nt], Al, Bh[kd][ks][2 * nt], Bh[kd][ks][2 * nt + 1]); // lh
                    mma_bf16(D[nt], Ah, Bl[kd][ks][2 * nt], Bl[kd][ks][2 * nt + 1]); // hl
                }
            }
        }

        #pragma unroll
        for (int t = 0; t < 3; ++t)
            #pragma unroll
            for (int e = 0; e < 4; ++e) mn[t][e] = fminf(mn[t][e], D[t][e]);

        build_st(d + 3, (d + 3) & 3);
        __syncthreads();
    }

    // ---- scatter min to sf[px128][28], bias + softmax ----
    float* sf = reinterpret_cast<float*>(sm);   // aliases X (reads done at last sync)
    {
        const int r0 = wid * 16 + (lane >> 2);
        const int c0 = (lane & 3) * 2;
        #pragma unroll
        for (int nt = 0; nt < 3; ++nt) {
            sf[r0 * 28 + nt * 8 + c0]           = mn[nt][0];
            sf[r0 * 28 + nt * 8 + c0 + 1]       = mn[nt][1];
            sf[(r0 + 8) * 28 + nt * 8 + c0]     = mn[nt][2];
            sf[(r0 + 8) * 28 + nt * 8 + c0 + 1] = mn[nt][3];
        }
    }
    __syncthreads();

    if (tid < 126) {
        float v[24];
        float m = -INF;
        #pragma unroll
        for (int c = 0; c < 24; ++c) {
            v[c] = sf[tid * 28 + c] + __ldg(&bias[c]);
            m = fmaxf(m, v[c]);
        }
        float s = 0.f;
        #pragma unroll
        for (int c = 0; c < 24; ++c) { v[c] = __expf(v[c] - m); s += v[c]; }
        const float inv = 1.0f / s;
        float* op = out + (size_t)n * 24 * 15876 + (size_t)h * 126 + tid;
        #pragma unroll
        for (int c = 0; c < 24; ++c)
            op[(size_t)c * 15876] = v[c] * inv;
    }
}

extern "C" void kernel_launch(void* const* d_in, const int* in_sizes, int n_in,
                              void* d_out, int out_size) {
    const float* x    = (const float*)d_in[0];
    const float* wgt  = (const float*)d_in[1];
    const float* bias = (const float*)d_in[2];
    float* out        = (float*)d_out;

    cudaFuncSetAttribute(conv_mma,
                         cudaFuncAttributeMaxDynamicSharedMemorySize, SMEM_TOTAL);

    dim3 grid(126, 16);   // (h, n)
    conv_mma<<<grid, 256, SMEM_TOTAL>>>(x, wgt, bias, out);
}

// round 12
// speedup vs baseline: 1.4347x; 1.1863x over previous
#include <cuda_runtime.h>
#include <cuda_bf16.h>
#include <math.h>

// mma.sync bf16 hi/lo split, A = x (M=px128), B = weights (N=co24, persistent regs).
// Build: dest-owned, 4x STS.128 per thread, XROW=64 with granule swizzle
// (g ^= (px>>1)&3) -> conflict-free ldsm + optimal wide stores.

typedef unsigned int u32;

#define XROW 64                          // 32 k * 2B, no pad (swizzled)
#define XPART (128 * XROW)               // 8192
#define XSLOT (2 * XPART)                // 16384 (hi+lo)
#define OFF_X 0
#define OFF_W (4 * XSLOT)                // 65536
#define WROW 64                          // 32 co * 2B
#define WPART (96 * WROW)                // 6144: [kd3][k32][co32]
#define SMEM_TOTAL (OFF_W + 2 * WPART + 64)   // 77888

__device__ __forceinline__ void ldsm4(u32* r, u32 a) {
    asm volatile("ldmatrix.sync.aligned.m8n8.x4.shared.b16 {%0,%1,%2,%3}, [%4];"
        : "=r"(r[0]), "=r"(r[1]), "=r"(r[2]), "=r"(r[3]) : "r"(a));
}
__device__ __forceinline__ void ldsm4t(u32* r, u32 a) {
    asm volatile("ldmatrix.sync.aligned.m8n8.x4.trans.shared.b16 {%0,%1,%2,%3}, [%4];"
        : "=r"(r[0]), "=r"(r[1]), "=r"(r[2]), "=r"(r[3]) : "r"(a));
}
__device__ __forceinline__ void ldsm2t(u32* r, u32 a) {
    asm volatile("ldmatrix.sync.aligned.m8n8.x2.trans.shared.b16 {%0,%1}, [%2];"
        : "=r"(r[0]), "=r"(r[1]) : "r"(a));
}
__device__ __forceinline__ void mma_bf16(float* d, const u32* a, u32 b0, u32 b1) {
    asm volatile(
        "mma.sync.aligned.m16n8k16.row.col.f32.bf16.bf16.f32 "
        "{%0,%1,%2,%3}, {%4,%5,%6,%7}, {%8,%9}, {%0,%1,%2,%3};"
        : "+f"(d[0]), "+f"(d[1]), "+f"(d[2]), "+f"(d[3])
        : "r"(a[0]), "r"(a[1]), "r"(a[2]), "r"(a[3]), "r"(b0), "r"(b1));
}
__device__ __forceinline__ void sts128(u32 a, u32 w0, u32 w1, u32 w2, u32 w3) {
    asm volatile("st.shared.v4.b32 [%0], {%1,%2,%3,%4};"
        :: "r"(a), "r"(w0), "r"(w1), "r"(w2), "r"(w3) : "memory");
}
__device__ __forceinline__ unsigned short bfb(float v) {
    __nv_bfloat16 t = __float2bfloat16(v);
    return reinterpret_cast<unsigned short&>(t);
}

extern "C" __global__ void __launch_bounds__(256, 2)
conv_mma(const float* __restrict__ x, const float* __restrict__ wgt,
         const float* __restrict__ bias, float* __restrict__ out)
{
    extern __shared__ char sm[];
    const u32 sb = (u32)__cvta_generic_to_shared(sm);
    const int tid  = threadIdx.x;
    const int lane = tid & 31;
    const int wid  = tid >> 5;
    const int h = blockIdx.x;
    const int n = blockIdx.y;

    // zero W region only (co 24-31 / k pads); X fully overwritten each build
    for (int i = tid; i < 2 * WPART / 16; i += 256)
        *reinterpret_cast<float4*>(sm + OFF_W + i * 16) = make_float4(0.f, 0.f, 0.f, 0.f);
    __syncthreads();

    // ---- weights -> smem bf16 hi/lo: W[part][kd][k][co], k=(ci*3+kh)*3+kw ----
    for (int e = tid; e < 1944; e += 256) {
        int co = e / 81, tap = e % 81;
        int ci = tap / 27;
        int kd = (tap % 27) / 9;
        int kh = (tap % 9) / 3;
        int kw = tap % 3;
        float v = wgt[e];
        __nv_bfloat16 hb = __float2bfloat16(v);
        __nv_bfloat16 lb = __float2bfloat16(v - __bfloat162float(hb));
        int row = kd * 32 + (ci * 3 + kh) * 3 + kw;
        *reinterpret_cast<__nv_bfloat16*>(sm + OFF_W +         row * WROW + co * 2) = hb;
        *reinterpret_cast<__nv_bfloat16*>(sm + OFF_W + WPART + row * WROW + co * 2) = lb;
    }

    // ---- dest-owned build: thread = (px, part); 4x STS.128 per slice ----
    const int bpx  = tid & 127;
    const int part = tid >> 7;
    const int bsw  = (bpx >> 1) & 3;            // granule swizzle for this px

    float pv[9];                                 // kw=0 row values (prefetch)
    auto build_ld = [&](int z) {
        if (z >= 32) return;
        #pragma unroll
        for (int r9 = 0; r9 < 9; ++r9) {
            int ci = r9 / 3, kh = r9 % 3;
            pv[r9] = __ldg(x + ((size_t)((n * 3 + ci) * 32 + z) << 14)
                             + ((h + kh) << 7) + bpx);
        }
    };
    auto build_st = [&](int z, int slot) {
        if (z >= 32) return;
        const u32 base = sb + OFF_X + (u32)(slot * XSLOT + part * XPART + bpx * 64);
        unsigned short hv[32];
        #pragma unroll
        for (int r9 = 0; r9 < 9; ++r9) {
            int ci = r9 / 3, kh = r9 % 3;
            const float* row = x + ((size_t)((n * 3 + ci) * 32 + z) << 14)
                                 + ((h + kh) << 7);
            int p1 = bpx + 1 < 128 ? bpx + 1 : 127;
            int p2 = bpx + 2 < 128 ? bpx + 2 : 127;
            float v0 = pv[r9];
            float v1 = __ldg(row + p1);          // L1 hit (line warmed by pv)
            float v2 = __ldg(row + p2);
            #pragma unroll
            for (int kw = 0; kw < 3; ++kw) {
                float v = (kw == 0) ? v0 : (kw == 1 ? v1 : v2);
                unsigned short b;
                if (part == 0) b = bfb(v);
                else {
                    __nv_bfloat16 hb = __float2bfloat16(v);
                    b = bfb(v - __bfloat162float(hb));
                }
                hv[r9 * 3 + kw] = b;
            }
        }
        #pragma unroll
        for (int k = 27; k < 32; ++k) hv[k] = 0;
        #pragma unroll
        for (int g = 0; g < 4; ++g) {
            u32 w0 = (u32)hv[8*g]     | ((u32)hv[8*g+1] << 16);
            u32 w1 = (u32)hv[8*g+2]   | ((u32)hv[8*g+3] << 16);
            u32 w2 = (u32)hv[8*g+4]   | ((u32)hv[8*g+5] << 16);
            u32 w3 = (u32)hv[8*g+6]   | ((u32)hv[8*g+7] << 16);
            sts128(base + (u32)((g ^ bsw) * 16), w0, w1, w2, w3);
        }
    };

    build_ld(0); build_st(0, 0);
    build_ld(1); build_st(1, 1);
    build_ld(2); build_st(2, 2);
    __syncthreads();

    // ---- persistent weight B-fragments ----
    u32 Bh[3][2][6], Bl[3][2][6];
    {
        const u32 wb = sb + OFF_W;
        const int krow = lane & 15;
        const int coo  = (lane >> 4) * 8;
        #pragma unroll
        for (int kd = 0; kd < 3; ++kd)
            #pragma unroll
            for (int ks = 0; ks < 2; ++ks) {
                u32 rbase = (u32)((kd * 32 + ks * 16 + krow) * WROW);
                ldsm4t(Bh[kd][ks],     wb + rbase + (u32)(coo * 2));
                ldsm2t(Bh[kd][ks] + 4, wb + rbase + 32);
                ldsm4t(Bl[kd][ks],     wb + WPART + rbase + (u32)(coo * 2));
                ldsm2t(Bl[kd][ks] + 4, wb + WPART + rbase + 32);
            }
    }

    // A-frag lane addressing (swizzled): row pxr, 16B granule (ks*2 + c0) ^ swr
    const int pxr = wid * 16 + (lane & 15);
    const int c0  = lane >> 4;
    const int swr = (pxr >> 1) & 3;
    const u32 arow  = sb + OFF_X + (u32)(pxr * 64);
    const u32 offk0 = (u32)(((c0)     ^ swr) * 16);   // ks=0: k0-15
    const u32 offk1 = (u32)(((2 + c0) ^ swr) * 16);   // ks=1: k16-31

    const float INF = __int_as_float(0x7f800000);
    float mn[3][4];
    #pragma unroll
    for (int t = 0; t < 3; ++t)
        #pragma unroll
        for (int e = 0; e < 4; ++e) mn[t][e] = INF;

    #pragma unroll 1
    for (int d = 0; d < 30; ++d) {
        build_ld(d + 3);                 // warm next slice (DRAM latency hidden)

        float D[3][4];
        #pragma unroll
        for (int t = 0; t < 3; ++t)
            #pragma unroll
            for (int e = 0; e < 4; ++e) D[t][e] = 0.f;

        #pragma unroll
        for (int kd = 0; kd < 3; ++kd) {
            const u32 sa = arow + (u32)(((d + kd) & 3) * XSLOT);
            #pragma unroll
            for (int ks = 0; ks < 2; ++ks) {
                const u32 off = ks ? offk1 : offk0;
                u32 Ah[4], Al[4];
                ldsm4(Ah, sa + off);
                ldsm4(Al, sa + (u32)XPART + off);
                #pragma unroll
                for (int nt = 0; nt < 3; ++nt) {
                    mma_bf16(D[nt], Ah, Bh[kd][ks][2*nt], Bh[kd][ks][2*nt+1]); // hh
                    mma_bf16(D[nt], Al, Bh[kd][ks][2*nt], Bh[kd][ks][2*nt+1]); // lh
                    mma_bf16(D[nt], Ah, Bl[kd][ks][2*nt], Bl[kd][ks][2*nt+1]); // hl
                }
            }
        }

        #pragma unroll
        for (int t = 0; t < 3; ++t)
            #pragma unroll
            for (int e = 0; e < 4; ++e) mn[t][e] = fminf(mn[t][e], D[t][e]);

        build_st(d + 3, (d + 3) & 3);
        __syncthreads();
    }

    // ---- scatter min to sf[px128][28], bias + softmax ----
    float* sf = reinterpret_cast<float*>(sm);    // aliases X (reads done)
    {
        const int r0 = wid * 16 + (lane >> 2);
        const int c0s = (lane & 3) * 2;
        #pragma unroll
        for (int nt = 0; nt < 3; ++nt) {
            sf[r0 * 28 + nt * 8 + c0s]           = mn[nt][0];
            sf[r0 * 28 + nt * 8 + c0s + 1]       = mn[nt][1];
            sf[(r0 + 8) * 28 + nt * 8 + c0s]     = mn[nt][2];
            sf[(r0 + 8) * 28 + nt * 8 + c0s + 1] = mn[nt][3];
        }
    }
    __syncthreads();

    if (tid < 126) {
        float v[24];
        float m = -INF;
        #pragma unroll
        for (int c = 0; c < 24; ++c) {
            v[c] = sf[tid * 28 + c] + __ldg(&bias[c]);
            m = fmaxf(m, v[c]);
        }
        float s = 0.f;
        #pragma unroll
        for (int c = 0; c < 24; ++c) { v[c] = __expf(v[c] - m); s += v[c]; }
        const float inv = 1.0f / s;
        float* op = out + (size_t)n * 24 * 15876 + (size_t)h * 126 + tid;
        #pragma unroll
        for (int c = 0; c < 24; ++c)
            op[(size_t)c * 15876] = v[c] * inv;
    }
}

extern "C" void kernel_launch(void* const* d_in, const int* in_sizes, int n_in,
                              void* d_out, int out_size) {
    const float* x    = (const float*)d_in[0];
    const float* wgt  = (const float*)d_in[1];
    const float* bias = (const float*)d_in[2];
    float* out        = (float*)d_out;

    cudaFuncSetAttribute(conv_mma,
                         cudaFuncAttributeMaxDynamicSharedMemorySize, SMEM_TOTAL);

    dim3 grid(126, 16);   // (h, n)
    conv_mma<<<grid, 256, SMEM_TOTAL>>>(x, wgt, bias, out);
}